// round 15
// baseline (speedup 1.0000x reference)
#include <cuda_runtime.h>
#include <cstdint>

// Shapes (fixed): B=8, L=256, F=512, U=512.
#define Bn 8
#define Ln 256
#define Fn 512
#define Un 512
#define Mn (Bn*Ln)   // 2048

// Scratch
__device__ __align__(16) float g_Q[Mn * Un];        // [2048][512]
__device__ __align__(16) float g_KT[Bn * Un * Ln];  // [8][512][256]  K+bh, u-major

__device__ __forceinline__ float tanh_approx(float x) {
    float y;
    asm("tanh.approx.f32 %0, %1;" : "=f"(y) : "f"(x));
    return y;
}

__device__ __forceinline__ uint32_t cvt_tf32(float x) {
    uint32_t r;
    asm("cvt.rna.tf32.f32 %0, %1;" : "=r"(r) : "f"(x));
    return r;
}

#define MMA_TF32(c, A0, A1, A2, A3, B0, B1)                                   \
    asm volatile(                                                             \
        "mma.sync.aligned.m16n8k8.row.col.f32.tf32.tf32.f32 "                 \
        "{%0,%1,%2,%3}, {%4,%5,%6,%7}, {%8,%9}, {%0,%1,%2,%3};"               \
        : "+f"((c)[0]), "+f"((c)[1]), "+f"((c)[2]), "+f"((c)[3])              \
        : "r"(A0), "r"(A1), "r"(A2), "r"(A3), "r"(B0), "r"(B1))

// ---------------------------------------------------------------------------
// Kernel 1: tensor-core projections, smem-staged (validated, 20-31us).
// ---------------------------------------------------------------------------
#define APITCH 20
#define BPITCH 136
#define A_FLOATS (2 * 128 * APITCH)
#define B_FLOATS (2 * 16 * BPITCH)

__global__ __launch_bounds__(256) void proj_tc_kernel(
    const float* __restrict__ X,    // [2048,512]
    const float* __restrict__ Wq,   // [512,512]
    const float* __restrict__ Wk,   // [512,512]
    const float* __restrict__ bh)   // [512]
{
    __shared__ __align__(16) float pool[A_FLOATS + B_FLOATS];
    typedef float ATile[128][APITCH];
    typedef float BTile[16][BPITCH];
    ATile* As = (ATile*)pool;
    BTile* Bs = (BTile*)(pool + A_FLOATS);
    typedef float KRow[65];
    KRow* kbuf = (KRow*)pool;   // epilogue alias

    const int bx  = blockIdx.x;
    const int isK = bx >> 6;
    const int m0  = ((bx >> 2) & 15) * 128;
    const int n0  = (bx & 3) * 128;
    const float* __restrict__ W = isK ? Wk : Wq;

    const int tid  = threadIdx.x;
    const int wid  = tid >> 5;
    const int lane = tid & 31;
    const int mw = wid >> 2;
    const int nw = wid & 3;
    const int gid = lane >> 2;
    const int tig = lane & 3;

    const int ma  = tid >> 2;
    const int k4a = (tid & 3) * 4;
    const int kb  = tid >> 5;
    const int n4b = (tid & 31) * 4;

    float acc[4][4][4];
#pragma unroll
    for (int i = 0; i < 4; i++)
#pragma unroll
        for (int j = 0; j < 4; j++)
#pragma unroll
            for (int r = 0; r < 4; r++) acc[i][j][r] = 0.f;

    float4 av0, av1, bv0, bv1;
#define PLOAD(K0)                                                             \
    do {                                                                      \
        av0 = *(const float4*)&X[(size_t)(m0 + ma) * Fn + (K0) + k4a];        \
        av1 = *(const float4*)&X[(size_t)(m0 + ma + 64) * Fn + (K0) + k4a];   \
        bv0 = *(const float4*)&W[(size_t)((K0) + kb) * Un + n0 + n4b];        \
        bv1 = *(const float4*)&W[(size_t)((K0) + kb + 8) * Un + n0 + n4b];    \
    } while (0)
#define PSTORE(S)                                                             \
    do {                                                                      \
        *(float4*)&As[S][ma][k4a]      = av0;                                 \
        *(float4*)&As[S][ma + 64][k4a] = av1;                                 \
        *(float4*)&Bs[S][kb][n4b]      = bv0;                                 \
        *(float4*)&Bs[S][kb + 8][n4b]  = bv1;                                 \
    } while (0)

    PLOAD(0);
    PSTORE(0);
    __syncthreads();

    for (int c = 0; c < 32; c++) {
        const int s = c & 1;
        if (c + 1 < 32) PLOAD((c + 1) * 16);
#pragma unroll
        for (int kk = 0; kk < 16; kk += 8) {
            uint32_t a[4][4], b[4][2];
#pragma unroll
            for (int mt = 0; mt < 4; mt++) {
                const int row = mw * 64 + mt * 16 + gid;
                a[mt][0] = cvt_tf32(As[s][row][kk + tig]);
                a[mt][1] = cvt_tf32(As[s][row + 8][kk + tig]);
                a[mt][2] = cvt_tf32(As[s][row][kk + tig + 4]);
                a[mt][3] = cvt_tf32(As[s][row + 8][kk + tig + 4]);
            }
#pragma unroll
            for (int nt = 0; nt < 4; nt++) {
                const int col = nw * 32 + nt * 8 + gid;
                b[nt][0] = cvt_tf32(Bs[s][kk + tig][col]);
                b[nt][1] = cvt_tf32(Bs[s][kk + tig + 4][col]);
            }
#pragma unroll
            for (int mt = 0; mt < 4; mt++)
#pragma unroll
                for (int nt = 0; nt < 4; nt++)
                    MMA_TF32(acc[mt][nt], a[mt][0], a[mt][1], a[mt][2],
                             a[mt][3], b[nt][0], b[nt][1]);
        }
        if (c + 1 < 32) {
            PSTORE((c + 1) & 1);
            __syncthreads();
        }
    }

    if (!isK) {
#pragma unroll
        for (int mt = 0; mt < 4; mt++) {
#pragma unroll
            for (int nt = 0; nt < 4; nt++) {
                const int row = m0 + mw * 64 + mt * 16 + gid;
                const int col = n0 + nw * 32 + nt * 8 + 2 * tig;
                float2 lo = make_float2(acc[mt][nt][0], acc[mt][nt][1]);
                float2 hi = make_float2(acc[mt][nt][2], acc[mt][nt][3]);
                *(float2*)&g_Q[(size_t)row * Un + col]       = lo;
                *(float2*)&g_Q[(size_t)(row + 8) * Un + col] = hi;
            }
        }
    } else {
        const int bidx = m0 >> 8;
        const int qi0  = m0 & 255;
#pragma unroll
        for (int pass = 0; pass < 2; pass++) {
            __syncthreads();
            if ((nw >> 1) == pass) {
#pragma unroll
                for (int mt = 0; mt < 4; mt++) {
#pragma unroll
                    for (int nt = 0; nt < 4; nt++) {
                        const int row = mw * 64 + mt * 16 + gid;
                        const int cl  = (nw & 1) * 32 + nt * 8 + 2 * tig;
                        kbuf[row][cl]         = acc[mt][nt][0];
                        kbuf[row][cl + 1]     = acc[mt][nt][1];
                        kbuf[row + 8][cl]     = acc[mt][nt][2];
                        kbuf[row + 8][cl + 1] = acc[mt][nt][3];
                    }
                }
            }
            __syncthreads();
#pragma unroll
            for (int i = tid; i < 64 * 128; i += 256) {
                const int ul = i >> 7;
                const int q  = i & 127;
                const int u  = n0 + pass * 64 + ul;
                g_KT[((size_t)bidx * Un + u) * Ln + qi0 + q] =
                    kbuf[q][ul] + __ldg(&bh[u]);
            }
        }
    }
#undef PLOAD
#undef PSTORE
}

// ---------------------------------------------------------------------------
// Kernel 2: fused attention. 512 CTAs x 256 threads, PT=4, 4 CTAs/SM.
// Warp w (0..7) owns q-block [w*32, w*32+32) x all 4 p rows.
// Lane = us(0..3)*8 + qk(0..7): in-warp u-split over 128-u chunks.
// Each thread: 4p x 4q x 128u = 16 tanh/iter. Partials reduced by 2 shfl
// rounds (no ep smem). Fused normalize + epilogue (2 f-cols/thread).
// ---------------------------------------------------------------------------
#define PT 4
#define QPITCH 516   // per-us stride for QsT: 128*4 + 4 (conflict-free, 16B-aligned)
#define WPITCH 129

__global__ __launch_bounds__(256, 4) void attn_kernel(
    const float* __restrict__ X,    // [8,256,512]
    const float* __restrict__ Wv,   // [512]
    float* __restrict__ out)        // [8,256,512]
{
    __shared__ float QsT[4 * QPITCH];   // [us][i 0..127][p 0..3]  8.3 KB
    __shared__ float Wvs[4 * WPITCH];   // [us][i]                 2.1 KB
    __shared__ float aP[PT][Ln];        // [p][q]                  4 KB
    __shared__ float aQ[Ln][PT];        // [q][p]                  4 KB

    const int tid  = threadIdx.x;
    const int b    = blockIdx.x >> 6;
    const int p0   = (blockIdx.x & 63) * PT;
    const int lane = tid & 31;
    const int wq   = tid >> 5;      // 0..7 -> 32-q block
    const int us   = lane >> 3;     // 0..3 -> 128-u chunk
    const int qk   = lane & 7;      // float4 index within q block

    // Stage Q ([us][i][p] padded) and Wv ([us][i] padded)
#pragma unroll
    for (int idx = tid; idx < PT * Un; idx += 256) {
        int p = idx >> 9;           // 0..3
        int u = idx & 511;
        QsT[(u >> 7) * QPITCH + (u & 127) * 4 + p] =
            g_Q[((size_t)b * Ln + p0 + p) * Un + u];
    }
#pragma unroll
    for (int u = tid; u < Un; u += 256)
        Wvs[(u >> 7) * WPITCH + (u & 127)] = Wv[u];
    __syncthreads();

    // ---- e-loop: 16 tanh / iter / thread ----
    const float4* __restrict__ kt4 =
        (const float4*)(g_KT + (size_t)b * Un * Ln) + (size_t)us * 128 * 64
        + wq * 8 + qk;
    const float* __restrict__ qb  = &QsT[us * QPITCH];
    const float* __restrict__ wvb = &Wvs[us * WPITCH];

    float4 e0 = make_float4(0.f,0.f,0.f,0.f), e1 = e0, e2 = e0, e3 = e0;
#pragma unroll 4
    for (int i = 0; i < 128; i++) {
        float4 kv = __ldg(&kt4[i * 64]);
        float4 q4 = *(const float4*)&qb[i * 4];
        float  wv = wvb[i];
        e0.x = fmaf(wv, tanh_approx(q4.x + kv.x), e0.x);
        e0.y = fmaf(wv, tanh_approx(q4.x + kv.y), e0.y);
        e0.z = fmaf(wv, tanh_approx(q4.x + kv.z), e0.z);
        e0.w = fmaf(wv, tanh_approx(q4.x + kv.w), e0.w);
        e1.x = fmaf(wv, tanh_approx(q4.y + kv.x), e1.x);
        e1.y = fmaf(wv, tanh_approx(q4.y + kv.y), e1.y);
        e1.z = fmaf(wv, tanh_approx(q4.y + kv.z), e1.z);
        e1.w = fmaf(wv, tanh_approx(q4.y + kv.w), e1.w);
        e2.x = fmaf(wv, tanh_approx(q4.z + kv.x), e2.x);
        e2.y = fmaf(wv, tanh_approx(q4.z + kv.y), e2.y);
        e2.z = fmaf(wv, tanh_approx(q4.z + kv.z), e2.z);
        e2.w = fmaf(wv, tanh_approx(q4.z + kv.w), e2.w);
        e3.x = fmaf(wv, tanh_approx(q4.w + kv.x), e3.x);
        e3.y = fmaf(wv, tanh_approx(q4.w + kv.y), e3.y);
        e3.z = fmaf(wv, tanh_approx(q4.w + kv.z), e3.z);
        e3.w = fmaf(wv, tanh_approx(q4.w + kv.w), e3.w);
    }
    // ba is a uniform shift of e -> cancels exactly in the exp-normalize.

    // In-warp reduce over us (lane bits 3,4)
#pragma unroll
    for (int off = 8; off <= 16; off <<= 1) {
        e0.x += __shfl_xor_sync(0xffffffffu, e0.x, off);
        e0.y += __shfl_xor_sync(0xffffffffu, e0.y, off);
        e0.z += __shfl_xor_sync(0xffffffffu, e0.z, off);
        e0.w += __shfl_xor_sync(0xffffffffu, e0.w, off);
        e1.x += __shfl_xor_sync(0xffffffffu, e1.x, off);
        e1.y += __shfl_xor_sync(0xffffffffu, e1.y, off);
        e1.z += __shfl_xor_sync(0xffffffffu, e1.z, off);
        e1.w += __shfl_xor_sync(0xffffffffu, e1.w, off);
        e2.x += __shfl_xor_sync(0xffffffffu, e2.x, off);
        e2.y += __shfl_xor_sync(0xffffffffu, e2.y, off);
        e2.z += __shfl_xor_sync(0xffffffffu, e2.z, off);
        e2.w += __shfl_xor_sync(0xffffffffu, e2.w, off);
        e3.x += __shfl_xor_sync(0xffffffffu, e3.x, off);
        e3.y += __shfl_xor_sync(0xffffffffu, e3.y, off);
        e3.z += __shfl_xor_sync(0xffffffffu, e3.z, off);
        e3.w += __shfl_xor_sync(0xffffffffu, e3.w, off);
    }
    if (us == 0) {
        const int qbase = wq * 32 + qk * 4;
        *(float4*)&aP[0][qbase] = e0;
        *(float4*)&aP[1][qbase] = e1;
        *(float4*)&aP[2][qbase] = e2;
        *(float4*)&aP[3][qbase] = e3;
    }
    __syncthreads();

    // ---- normalize: warp w (< 4) handles row p = w ----
    {
        const int w = tid >> 5, l = tid & 31;
        if (w < PT) {
            float v[8];
            float m = -1e30f;
#pragma unroll
            for (int j = 0; j < 8; j++) {
                v[j] = aP[w][l + j * 32];
                m = fmaxf(m, v[j]);
            }
#pragma unroll
            for (int o = 16; o > 0; o >>= 1)
                m = fmaxf(m, __shfl_xor_sync(0xffffffffu, m, o));
            float s = 0.f;
#pragma unroll
            for (int j = 0; j < 8; j++) {
                v[j] = __expf(v[j] - m);
                s += v[j];
            }
#pragma unroll
            for (int o = 16; o > 0; o >>= 1)
                s += __shfl_xor_sync(0xffffffffu, s, o);
            float inv = 1.f / (s + 1e-7f);
#pragma unroll
            for (int j = 0; j < 8; j++) aP[w][l + j * 32] = v[j] * inv;
        }
    }
    __syncthreads();

    // ---- transpose aP[p][q] -> aQ[q][p] ----
#pragma unroll
    for (int i = tid; i < PT * Ln; i += 256) {
        int p = i >> 8;
        int q = i & 255;
        aQ[q][p] = aP[p][q];
    }
    __syncthreads();

    // ---- fused epilogue: out[p,f] = sum_q a[p][q]*X[b,q,f]; f = tid, tid+256
    float o0[PT], o1[PT];
#pragma unroll
    for (int p = 0; p < PT; p++) { o0[p] = 0.f; o1[p] = 0.f; }

    const float* __restrict__ xin = X + (size_t)b * Ln * Fn;
#pragma unroll 2
    for (int q = 0; q < Ln; q++) {
        float x0 = __ldg(&xin[q * Fn + tid]);
        float x1 = __ldg(&xin[q * Fn + tid + 256]);
        float4 a4 = *(const float4*)&aQ[q][0];   // warp-uniform broadcast
        o0[0] = fmaf(a4.x, x0, o0[0]); o1[0] = fmaf(a4.x, x1, o1[0]);
        o0[1] = fmaf(a4.y, x0, o0[1]); o1[1] = fmaf(a4.y, x1, o1[1]);
        o0[2] = fmaf(a4.z, x0, o0[2]); o1[2] = fmaf(a4.z, x1, o1[2]);
        o0[3] = fmaf(a4.w, x0, o0[3]); o1[3] = fmaf(a4.w, x1, o1[3]);
    }
#pragma unroll
    for (int p = 0; p < PT; p++) {
        out[((size_t)b * Ln + p0 + p) * Fn + tid]       = o0[p];
        out[((size_t)b * Ln + p0 + p) * Fn + tid + 256] = o1[p];
    }
}

extern "C" void kernel_launch(void* const* d_in, const int* in_sizes, int n_in,
                              void* d_out, int out_size) {
    const float* X  = (const float*)d_in[0];
    const float* Wq = (const float*)d_in[1];
    const float* Wk = (const float*)d_in[2];
    const float* Wv = (const float*)d_in[3];
    const float* bh = (const float*)d_in[4];
    // d_in[5] = ba: cancels exactly in the exp-normalize; unused.
    float* out = (float*)d_out;

    proj_tc_kernel<<<128, 256>>>(X, Wq, Wk, bh);       // 128 CTAs

    attn_kernel<<<Bn * (Ln / PT), 256>>>(X, Wv, out);  // 512 CTAs x 256 thr
}

// round 16
// speedup vs baseline: 1.0192x; 1.0192x over previous
#include <cuda_runtime.h>
#include <cstdint>

// Shapes (fixed): B=8, L=256, F=512, U=512.
#define Bn 8
#define Ln 256
#define Fn 512
#define Un 512
#define Mn (Bn*Ln)   // 2048

// Scratch
__device__ __align__(16) float g_Q[Mn * Un];        // [2048][512]
__device__ __align__(16) float g_KT[Bn * Un * Ln];  // [8][512][256]  K+bh, u-major

__device__ __forceinline__ float tanh_approx(float x) {
    float y;
    asm("tanh.approx.f32 %0, %1;" : "=f"(y) : "f"(x));
    return y;
}

__device__ __forceinline__ uint32_t cvt_tf32(float x) {
    uint32_t r;
    asm("cvt.rna.tf32.f32 %0, %1;" : "=r"(r) : "f"(x));
    return r;
}

#define MMA_TF32(c, A0, A1, A2, A3, B0, B1)                                   \
    asm volatile(                                                             \
        "mma.sync.aligned.m16n8k8.row.col.f32.tf32.tf32.f32 "                 \
        "{%0,%1,%2,%3}, {%4,%5,%6,%7}, {%8,%9}, {%0,%1,%2,%3};"               \
        : "+f"((c)[0]), "+f"((c)[1]), "+f"((c)[2]), "+f"((c)[3])              \
        : "r"(A0), "r"(A1), "r"(A2), "r"(A3), "r"(B0), "r"(B1))

// ---------------------------------------------------------------------------
// Kernel 1: tensor-core projections, 64x128 tiles -> 256 CTAs (fills all SMs).
// bx>>7 selects output (0=Q/Wq, 1=K/Wk); (bx>>2)&31 = m-tile, bx&3 = n-tile.
// Double-buffered smem As[2][64][20] / Bs[2][16][136] (conflict-free).
// 8 warps as 2m x 4n; warp tile 32x32 = 2x4 m16n8k8 tf32 MMAs per k-step.
// ---------------------------------------------------------------------------
#define APITCH 20
#define BPITCH 136
#define A_FLOATS (2 * 64 * APITCH)    // 2560
#define B_FLOATS (2 * 16 * BPITCH)    // 4352
#define POOL_FLOATS 8320              // max(A+B, 64*130 kbuf)

__global__ __launch_bounds__(256) void proj_tc_kernel(
    const float* __restrict__ X,    // [2048,512]
    const float* __restrict__ Wq,   // [512,512]
    const float* __restrict__ Wk,   // [512,512]
    const float* __restrict__ bh)   // [512]
{
    __shared__ __align__(16) float pool[POOL_FLOATS];   // 33.3 KB
    typedef float ATile[64][APITCH];
    typedef float BTile[16][BPITCH];
    ATile* As = (ATile*)pool;
    BTile* Bs = (BTile*)(pool + A_FLOATS);
    typedef float KRow[130];
    KRow* kbuf = (KRow*)pool;   // epilogue alias: 64 x 130 floats

    const int bx  = blockIdx.x;
    const int isK = bx >> 7;
    const int m0  = ((bx >> 2) & 31) * 64;
    const int n0  = (bx & 3) * 128;
    const float* __restrict__ W = isK ? Wk : Wq;

    const int tid  = threadIdx.x;
    const int wid  = tid >> 5;
    const int lane = tid & 31;
    const int mw = wid >> 2;        // 0..1 -> 32-row half
    const int nw = wid & 3;         // 0..3 -> 32-col block
    const int gid = lane >> 2;      // 0..7
    const int tig = lane & 3;       // 0..3

    const int a_row = tid >> 2;         // 0..63
    const int a_k4  = (tid & 3) * 4;
    const int kb    = tid >> 5;         // 0..7
    const int n4b   = (tid & 31) * 4;

    float acc[2][4][4];
#pragma unroll
    for (int i = 0; i < 2; i++)
#pragma unroll
        for (int j = 0; j < 4; j++)
#pragma unroll
            for (int r = 0; r < 4; r++) acc[i][j][r] = 0.f;

    float4 av, bv0, bv1;
#define PLOAD(K0)                                                             \
    do {                                                                      \
        av  = *(const float4*)&X[(size_t)(m0 + a_row) * Fn + (K0) + a_k4];    \
        bv0 = *(const float4*)&W[(size_t)((K0) + kb) * Un + n0 + n4b];        \
        bv1 = *(const float4*)&W[(size_t)((K0) + kb + 8) * Un + n0 + n4b];    \
    } while (0)
#define PSTORE(S)                                                             \
    do {                                                                      \
        *(float4*)&As[S][a_row][a_k4]  = av;                                  \
        *(float4*)&Bs[S][kb][n4b]      = bv0;                                 \
        *(float4*)&Bs[S][kb + 8][n4b]  = bv1;                                 \
    } while (0)

    PLOAD(0);
    PSTORE(0);
    __syncthreads();

    for (int c = 0; c < 32; c++) {
        const int s = c & 1;
        if (c + 1 < 32) PLOAD((c + 1) * 16);
#pragma unroll
        for (int kk = 0; kk < 16; kk += 8) {
            uint32_t a[2][4], b[4][2];
#pragma unroll
            for (int mt = 0; mt < 2; mt++) {
                const int row = mw * 32 + mt * 16 + gid;
                a[mt][0] = cvt_tf32(As[s][row][kk + tig]);
                a[mt][1] = cvt_tf32(As[s][row + 8][kk + tig]);
                a[mt][2] = cvt_tf32(As[s][row][kk + tig + 4]);
                a[mt][3] = cvt_tf32(As[s][row + 8][kk + tig + 4]);
            }
#pragma unroll
            for (int nt = 0; nt < 4; nt++) {
                const int col = nw * 32 + nt * 8 + gid;
                b[nt][0] = cvt_tf32(Bs[s][kk + tig][col]);
                b[nt][1] = cvt_tf32(Bs[s][kk + tig + 4][col]);
            }
#pragma unroll
            for (int mt = 0; mt < 2; mt++)
#pragma unroll
                for (int nt = 0; nt < 4; nt++)
                    MMA_TF32(acc[mt][nt], a[mt][0], a[mt][1], a[mt][2],
                             a[mt][3], b[nt][0], b[nt][1]);
        }
        if (c + 1 < 32) {
            PSTORE((c + 1) & 1);
            __syncthreads();
        }
    }

    if (!isK) {
        // Q epilogue: direct row-major float2 stores
#pragma unroll
        for (int mt = 0; mt < 2; mt++) {
#pragma unroll
            for (int nt = 0; nt < 4; nt++) {
                const int row = m0 + mw * 32 + mt * 16 + gid;
                const int col = n0 + nw * 32 + nt * 8 + 2 * tig;
                float2 lo = make_float2(acc[mt][nt][0], acc[mt][nt][1]);
                float2 hi = make_float2(acc[mt][nt][2], acc[mt][nt][3]);
                *(float2*)&g_Q[(size_t)row * Un + col]       = lo;
                *(float2*)&g_Q[(size_t)(row + 8) * Un + col] = hi;
            }
        }
    } else {
        // K epilogue: single-pass 64x128 transpose via kbuf, +bh, store KT.
        const int bidx = m0 >> 8;
        const int qi0  = m0 & 255;
        __syncthreads();
#pragma unroll
        for (int mt = 0; mt < 2; mt++) {
#pragma unroll
            for (int nt = 0; nt < 4; nt++) {
                const int row = mw * 32 + mt * 16 + gid;
                const int cl  = nw * 32 + nt * 8 + 2 * tig;
                kbuf[row][cl]         = acc[mt][nt][0];
                kbuf[row][cl + 1]     = acc[mt][nt][1];
                kbuf[row + 8][cl]     = acc[mt][nt][2];
                kbuf[row + 8][cl + 1] = acc[mt][nt][3];
            }
        }
        __syncthreads();
#pragma unroll
        for (int i = tid; i < 128 * 64; i += 256) {
            const int ul = i >> 6;      // 0..127
            const int q  = i & 63;
            const int u  = n0 + ul;
            g_KT[((size_t)bidx * Un + u) * Ln + qi0 + q] =
                kbuf[q][ul] + __ldg(&bh[u]);
        }
    }
#undef PLOAD
#undef PSTORE
}

// ---------------------------------------------------------------------------
// Kernel 2: fused attention (R12 measured-best structure, unroll 4 -> 8).
// 256 CTAs x 512 threads, PT=8. Warp w: wq=w&7 -> 32-q block, wp=w>>3 -> 4
// p-rows. Lane = us(0..3)*8 + qk(0..7): in-warp u-split over 128-u chunks.
// 16 tanh/iter; partials reduced by 2 shfl rounds; fused normalize+epilogue.
// ---------------------------------------------------------------------------
#define PT 8

__global__ __launch_bounds__(512, 2) void attn_kernel(
    const float* __restrict__ X,    // [8,256,512]
    const float* __restrict__ Wv,   // [512]
    float* __restrict__ out)        // [8,256,512]
{
    __shared__ float QsT[4 * 1032];   // [us][i 0..127][p 0..7] (+8 pad/us)
    __shared__ float Wvs[4 * 129];    // [us][i] (+1 pad/us)
    __shared__ float aP[PT][Ln];      // [p][q]
    __shared__ float aQ[Ln][PT];      // [q][p]

    const int tid  = threadIdx.x;
    const int b    = blockIdx.x >> 5;
    const int p0   = (blockIdx.x & 31) * PT;
    const int lane = tid & 31;
    const int w    = tid >> 5;      // 0..15
    const int wq   = w & 7;         // 32-q block
    const int wp   = w >> 3;        // 0..1 -> p rows wp*4..wp*4+3
    const int us   = lane >> 3;     // 0..3 -> u chunk
    const int qk   = lane & 7;      // float4 index within 32-q block

    // Stage Q (padded-transposed) and Wv
#pragma unroll
    for (int idx = tid; idx < PT * Un; idx += 512) {
        int p = idx >> 9;           // 0..7
        int u = idx & 511;
        QsT[(u >> 7) * 1032 + (u & 127) * 8 + p] =
            g_Q[((size_t)b * Ln + p0 + p) * Un + u];
    }
    if (tid < Un) Wvs[(tid >> 7) * 129 + (tid & 127)] = Wv[tid];
    __syncthreads();

    // ---- e-loop: 16 tanh / iter / thread, MLP-8 ----
    const float4* __restrict__ kt4 =
        (const float4*)(g_KT + (size_t)b * Un * Ln) + (size_t)us * 128 * 64
        + wq * 8 + qk;
    const float* __restrict__ qb  = &QsT[us * 1032 + wp * 4];
    const float* __restrict__ wvb = &Wvs[us * 129];

    float4 e0 = make_float4(0.f,0.f,0.f,0.f), e1 = e0, e2 = e0, e3 = e0;
#pragma unroll 8
    for (int i = 0; i < 128; i++) {
        float4 kv = __ldg(&kt4[i * 64]);
        float4 q4 = *(const float4*)&qb[i * 8];
        float  wv = wvb[i];
        e0.x = fmaf(wv, tanh_approx(q4.x + kv.x), e0.x);
        e0.y = fmaf(wv, tanh_approx(q4.x + kv.y), e0.y);
        e0.z = fmaf(wv, tanh_approx(q4.x + kv.z), e0.z);
        e0.w = fmaf(wv, tanh_approx(q4.x + kv.w), e0.w);
        e1.x = fmaf(wv, tanh_approx(q4.y + kv.x), e1.x);
        e1.y = fmaf(wv, tanh_approx(q4.y + kv.y), e1.y);
        e1.z = fmaf(wv, tanh_approx(q4.y + kv.z), e1.z);
        e1.w = fmaf(wv, tanh_approx(q4.y + kv.w), e1.w);
        e2.x = fmaf(wv, tanh_approx(q4.z + kv.x), e2.x);
        e2.y = fmaf(wv, tanh_approx(q4.z + kv.y), e2.y);
        e2.z = fmaf(wv, tanh_approx(q4.z + kv.z), e2.z);
        e2.w = fmaf(wv, tanh_approx(q4.z + kv.w), e2.w);
        e3.x = fmaf(wv, tanh_approx(q4.w + kv.x), e3.x);
        e3.y = fmaf(wv, tanh_approx(q4.w + kv.y), e3.y);
        e3.z = fmaf(wv, tanh_approx(q4.w + kv.z), e3.z);
        e3.w = fmaf(wv, tanh_approx(q4.w + kv.w), e3.w);
    }
    // ba is a uniform shift of e -> cancels exactly in the exp-normalize.

    // In-warp reduce over us (lane bits 3,4)
#pragma unroll
    for (int off = 8; off <= 16; off <<= 1) {
        e0.x += __shfl_xor_sync(0xffffffffu, e0.x, off);
        e0.y += __shfl_xor_sync(0xffffffffu, e0.y, off);
        e0.z += __shfl_xor_sync(0xffffffffu, e0.z, off);
        e0.w += __shfl_xor_sync(0xffffffffu, e0.w, off);
        e1.x += __shfl_xor_sync(0xffffffffu, e1.x, off);
        e1.y += __shfl_xor_sync(0xffffffffu, e1.y, off);
        e1.z += __shfl_xor_sync(0xffffffffu, e1.z, off);
        e1.w += __shfl_xor_sync(0xffffffffu, e1.w, off);
        e2.x += __shfl_xor_sync(0xffffffffu, e2.x, off);
        e2.y += __shfl_xor_sync(0xffffffffu, e2.y, off);
        e2.z += __shfl_xor_sync(0xffffffffu, e2.z, off);
        e2.w += __shfl_xor_sync(0xffffffffu, e2.w, off);
        e3.x += __shfl_xor_sync(0xffffffffu, e3.x, off);
        e3.y += __shfl_xor_sync(0xffffffffu, e3.y, off);
        e3.z += __shfl_xor_sync(0xffffffffu, e3.z, off);
        e3.w += __shfl_xor_sync(0xffffffffu, e3.w, off);
    }
    if (us == 0) {
        const int qbase = wq * 32 + qk * 4;
        *(float4*)&aP[wp * 4 + 0][qbase] = e0;
        *(float4*)&aP[wp * 4 + 1][qbase] = e1;
        *(float4*)&aP[wp * 4 + 2][qbase] = e2;
        *(float4*)&aP[wp * 4 + 3][qbase] = e3;
    }
    __syncthreads();

    // ---- normalize: warp ww (< 8) handles row p = ww ----
    {
        const int ww = tid >> 5, l = tid & 31;
        if (ww < PT) {
            float v[8];
            float m = -1e30f;
#pragma unroll
            for (int j = 0; j < 8; j++) {
                v[j] = aP[ww][l + j * 32];
                m = fmaxf(m, v[j]);
            }
#pragma unroll
            for (int o = 16; o > 0; o >>= 1)
                m = fmaxf(m, __shfl_xor_sync(0xffffffffu, m, o));
            float s = 0.f;
#pragma unroll
            for (int j = 0; j < 8; j++) {
                v[j] = __expf(v[j] - m);
                s += v[j];
            }
#pragma unroll
            for (int o = 16; o > 0; o >>= 1)
                s += __shfl_xor_sync(0xffffffffu, s, o);
            float inv = 1.f / (s + 1e-7f);
#pragma unroll
            for (int j = 0; j < 8; j++) aP[ww][l + j * 32] = v[j] * inv;
        }
    }
    __syncthreads();

    // ---- transpose aP[p][q] -> aQ[q][p] ----
#pragma unroll
    for (int i = tid; i < PT * Ln; i += 512) {
        int p = i >> 8;
        int q = i & 255;
        aQ[q][p] = aP[p][q];
    }
    __syncthreads();

    // ---- fused epilogue: out[p,f] = sum_q a[p][q] * X[b,q,f]; f = tid ----
    float o[PT];
#pragma unroll
    for (int p = 0; p < PT; p++) o[p] = 0.f;

    const float* __restrict__ xin = X + (size_t)b * Ln * Fn;
#pragma unroll 2
    for (int q = 0; q < Ln; q++) {
        float x = __ldg(&xin[q * Fn + tid]);
        float4 aa = *(const float4*)&aQ[q][0];   // warp-uniform broadcast
        float4 ab = *(const float4*)&aQ[q][4];
        o[0] = fmaf(aa.x, x, o[0]);
        o[1] = fmaf(aa.y, x, o[1]);
        o[2] = fmaf(aa.z, x, o[2]);
        o[3] = fmaf(aa.w, x, o[3]);
        o[4] = fmaf(ab.x, x, o[4]);
        o[5] = fmaf(ab.y, x, o[5]);
        o[6] = fmaf(ab.z, x, o[6]);
        o[7] = fmaf(ab.w, x, o[7]);
    }
#pragma unroll
    for (int p = 0; p < PT; p++)
        out[((size_t)b * Ln + p0 + p) * Fn + tid] = o[p];
}

extern "C" void kernel_launch(void* const* d_in, const int* in_sizes, int n_in,
                              void* d_out, int out_size) {
    const float* X  = (const float*)d_in[0];
    const float* Wq = (const float*)d_in[1];
    const float* Wk = (const float*)d_in[2];
    const float* Wv = (const float*)d_in[3];
    const float* bh = (const float*)d_in[4];
    // d_in[5] = ba: cancels exactly in the exp-normalize; unused.
    float* out = (float*)d_out;

    proj_tc_kernel<<<256, 256>>>(X, Wq, Wk, bh);       // 256 CTAs (64x128 tiles)

    attn_kernel<<<Bn * (Ln / PT), 512>>>(X, Wv, out);  // 256 CTAs x 512 thr
}